// round 13
// baseline (speedup 1.0000x reference)
#include <cuda_runtime.h>
#include <cuda_bf16.h>
#include <cstdint>

#define SHIFT 4
#define NR 225
#define AS 132
#define ES 36
#define TS 40
#define SCALE 0.17677669529663687f

#define SA_B   0
#define QEB_B  67584
#define KEB_B  86016
#define VEB_B  104448
#define QH_B   122880
#define QL_B   133120
#define KH_B   143360
#define KL_B   153600
#define VTH_B  163840
#define VTL_B  172544
#define OE_B   181248
#define SMEM_BYTES 199680
#define AH_B   67584
#define AL_B   122880

__device__ __forceinline__ void mma_bf16(float* d, uint32_t a0, uint32_t a1, uint32_t a2, uint32_t a3,
                                         uint32_t b0, uint32_t b1) {
    asm volatile(
        "mma.sync.aligned.m16n8k16.row.col.f32.bf16.bf16.f32 "
        "{%0,%1,%2,%3},{%4,%5,%6,%7},{%8,%9},{%0,%1,%2,%3};"
        : "+f"(d[0]), "+f"(d[1]), "+f"(d[2]), "+f"(d[3])
        : "r"(a0), "r"(a1), "r"(a2), "r"(a3), "r"(b0), "r"(b1));
}
__device__ __forceinline__ uint32_t pkhi(float a, float b) {
    __nv_bfloat162 t = __floats2bfloat162_rn(a, b);
    return *reinterpret_cast<uint32_t*>(&t);
}
__device__ __forceinline__ uint32_t pklo(float a, float b) {
    float ha = __bfloat162float(__float2bfloat16(a));
    float hb = __bfloat162float(__float2bfloat16(b));
    __nv_bfloat162 t = __floats2bfloat162_rn(a - ha, b - hb);
    return *reinterpret_cast<uint32_t*>(&t);
}
__device__ __forceinline__ float2 rec2(uint32_t h, uint32_t l) {
    float2 a = __bfloat1622float2(*reinterpret_cast<__nv_bfloat162*>(&h));
    float2 b = __bfloat1622float2(*reinterpret_cast<__nv_bfloat162*>(&l));
    return make_float2(a.x + b.x, a.y + b.y);
}
__device__ __forceinline__ float2 upk(uint32_t h) {
    return __bfloat1622float2(*reinterpret_cast<__nv_bfloat162*>(&h));
}

__global__ __launch_bounds__(512, 1)
void swin_attn_kernel(const float* __restrict__ qkv,
                      const float* __restrict__ mask,
                      const float* __restrict__ rpe,
                      float* __restrict__ out)
{
    extern __shared__ char smc[];
    float* sA  = (float*)(smc + SA_B);
    __nv_bfloat16* QEb = (__nv_bfloat16*)(smc + QEB_B);
    __nv_bfloat16* KEb = (__nv_bfloat16*)(smc + KEB_B);
    __nv_bfloat16* VEb = (__nv_bfloat16*)(smc + VEB_B);
    float* sOE = (float*)(smc + OE_B);
    uint32_t* QHu = (uint32_t*)(smc + QH_B);
    uint32_t* QLu = (uint32_t*)(smc + QL_B);
    uint32_t* KHu = (uint32_t*)(smc + KH_B);
    uint32_t* KLu = (uint32_t*)(smc + KL_B);
    uint32_t* AHu = (uint32_t*)(smc + AH_B);
    uint32_t* ALu = (uint32_t*)(smc + AL_B);
    uint32_t* VTHu = (uint32_t*)(smc + VTH_B);
    uint32_t* VTLu = (uint32_t*)(smc + VTL_B);

    const int tid = threadIdx.x, wid = tid >> 5, lane = tid & 31;
    const int h   = blockIdx.y;
    const int b   = blockIdx.x >> 8;
    const int win = blockIdx.x & 255;
    const int wi  = win >> 4, wj = win & 15;

    // ---- load q,k,v (4 threads/token, 8 floats each) ----
    {
        const int t = tid >> 2, quarter = tid & 3;
        const int wh = t >> 4, ww = (t >> 1) & 7, n = t & 1;
        const int gy = (wi*8 + wh + SHIFT) & 127;
        const int gx = (wj*8 + ww + SHIFT) & 127;
        const float* base = qkv + (size_t)((((b*128 + gy)*128 + gx)*2 + n)*384) + h*32 + quarter*8;
        #pragma unroll
        for (int c4 = 0; c4 < 2; c4++) {
            float4 q = ((const float4*)base)[c4];
            float4 k = ((const float4*)(base + 128))[c4];
            float4 v = ((const float4*)(base + 256))[c4];
            q.x *= SCALE; q.y *= SCALE; q.z *= SCALE; q.w *= SCALE;
            const int u = t*20 + quarter*4 + c4*2;
            QHu[u]   = pkhi(q.x, q.y); QHu[u+1] = pkhi(q.z, q.w);
            QLu[u]   = pklo(q.x, q.y); QLu[u+1] = pklo(q.z, q.w);
            KHu[u]   = pkhi(k.x, k.y); KHu[u+1] = pkhi(k.z, k.w);
            KLu[u]   = pklo(k.x, k.y); KLu[u+1] = pklo(k.z, k.w);
            float vv[4] = {v.x, v.y, v.z, v.w};
            #pragma unroll
            for (int e = 0; e < 4; e++) {
                const int c = quarter*8 + c4*4 + e;
                __nv_bfloat16 hi = __float2bfloat16(vv[e]);
                __nv_bfloat16 lo = __float2bfloat16(vv[e] - __bfloat162float(hi));
                ((__nv_bfloat16*)VTHu)[c*136 + t] = hi;
                ((__nv_bfloat16*)VTLu)[c*136 + t] = lo;
            }
        }
    }
    // ---- rel-pos tables -> bf16 ----
    for (int idx = tid; idx < NR*24; idx += 512) {
        const int r = idx / 24, s = idx % 24;
        const int sl = s >> 3, c4 = s & 7;
        float4 v = *(const float4*)(rpe + (size_t)r*384 + h*96 + sl*32 + c4*4);
        __nv_bfloat16* dst = (sl == 0) ? QEb : (sl == 1) ? KEb : VEb;
        if (sl == 0) { v.x *= SCALE; v.y *= SCALE; v.z *= SCALE; v.w *= SCALE; }
        uint2 pk;
        pk.x = pkhi(v.x, v.y); pk.y = pkhi(v.z, v.w);
        *(uint2*)(dst + r*TS + c4*4) = pk;
    }
    __syncthreads();

    // ---- pass 1: qk via mma.sync (16 warps: 16-row x 64-col tiles), +mask -> sA ----
    {
        const int rblk = (wid >> 1)*16, nh = (wid & 1)*8;
        const int r = lane >> 2, cq = lane & 3;
        uint32_t ah[2][4], al[2][4];
        #pragma unroll
        for (int kt = 0; kt < 2; kt++) {
            const int base0 = (rblk + r)*20 + kt*8 + cq;
            const int base1 = (rblk + r + 8)*20 + kt*8 + cq;
            ah[kt][0] = QHu[base0];     ah[kt][1] = QHu[base1];
            ah[kt][2] = QHu[base0 + 4]; ah[kt][3] = QHu[base1 + 4];
            al[kt][0] = QLu[base0];     al[kt][1] = QLu[base1];
            al[kt][2] = QLu[base0 + 4]; al[kt][3] = QLu[base1 + 4];
        }
        const float* mrow = mask + (size_t)win*16384;
        #pragma unroll
        for (int nt = nh; nt < nh + 8; nt++) {
            float d[4] = {0.f, 0.f, 0.f, 0.f};
            #pragma unroll
            for (int kt = 0; kt < 2; kt++) {
                const int bidx = (nt*8 + r)*20 + kt*8 + cq;
                uint32_t bh0 = KHu[bidx], bh1 = KHu[bidx + 4];
                uint32_t bl0 = KLu[bidx], bl1 = KLu[bidx + 4];
                mma_bf16(d, ah[kt][0], ah[kt][1], ah[kt][2], ah[kt][3], bh0, bh1);
                mma_bf16(d, al[kt][0], al[kt][1], al[kt][2], al[kt][3], bh0, bh1);
                mma_bf16(d, ah[kt][0], ah[kt][1], ah[kt][2], ah[kt][3], bl0, bl1);
            }
            const int j0 = nt*8 + cq*2;
            const int i0 = rblk + r, i1 = rblk + r + 8;
            float2 m0 = *(const float2*)(mrow + i0*128 + j0);
            float2 m1 = *(const float2*)(mrow + i1*128 + j0);
            *(float2*)(sA + i0*AS + j0) = make_float2(d[0] + m0.x, d[1] + m0.y);
            *(float2*)(sA + i1*AS + j0) = make_float2(d[2] + m1.x, d[3] + m1.y);
        }
    }
    __syncthreads();

    // ---- pass 2: qr term (8 threads/pixel-pair, 8 pj each) ----
    {
        const int p = tid >> 3, pj0 = (tid & 7) << 3;
        const int phi = p >> 3, pwi = p & 7, i0 = 2*p;
        float4 q0[8], q1[8];
        #pragma unroll
        for (int c4 = 0; c4 < 8; c4++) {
            float2 xy = rec2(QHu[i0*20 + c4*2],     QLu[i0*20 + c4*2]);
            float2 zw = rec2(QHu[i0*20 + c4*2 + 1], QLu[i0*20 + c4*2 + 1]);
            q0[c4] = make_float4(xy.x, xy.y, zw.x, zw.y);
            xy = rec2(QHu[(i0+1)*20 + c4*2],     QLu[(i0+1)*20 + c4*2]);
            zw = rec2(QHu[(i0+1)*20 + c4*2 + 1], QLu[(i0+1)*20 + c4*2 + 1]);
            q1[c4] = make_float4(xy.x, xy.y, zw.x, zw.y);
        }
        #pragma unroll 4
        for (int pj = pj0; pj < pj0 + 8; pj++) {
            const int r = (phi - (pj >> 3) + 7)*15 + (pwi - (pj & 7) + 7);
            float s0 = 0.f, s1 = 0.f;
            #pragma unroll
            for (int c4 = 0; c4 < 8; c4++) {
                uint2 e = *(const uint2*)(KEb + r*TS + c4*4);
                float2 e01 = upk(e.x), e23 = upk(e.y);
                s0 += q0[c4].x*e01.x + q0[c4].y*e01.y + q0[c4].z*e23.x + q0[c4].w*e23.y;
                s1 += q1[c4].x*e01.x + q1[c4].y*e01.y + q1[c4].z*e23.x + q1[c4].w*e23.y;
            }
            float2* d0 = (float2*)(sA + i0*AS + 2*pj);
            float2* d1 = (float2*)(sA + (i0+1)*AS + 2*pj);
            float2 t0 = *d0, t1 = *d1;
            t0.x += s0; t0.y += s0; *d0 = t0;
            t1.x += s1; t1.y += s1; *d1 = t1;
        }
    }
    __syncthreads();

    // ---- pass 3: kr term ----
    {
        const int p = tid >> 3, pi0 = (tid & 7) << 3;
        const int phj = p >> 3, pwj = p & 7, j0 = 2*p;
        float4 k0[8], k1[8];
        #pragma unroll
        for (int c4 = 0; c4 < 8; c4++) {
            float2 xy = rec2(KHu[j0*20 + c4*2],     KLu[j0*20 + c4*2]);
            float2 zw = rec2(KHu[j0*20 + c4*2 + 1], KLu[j0*20 + c4*2 + 1]);
            k0[c4] = make_float4(xy.x, xy.y, zw.x, zw.y);
            xy = rec2(KHu[(j0+1)*20 + c4*2],     KLu[(j0+1)*20 + c4*2]);
            zw = rec2(KHu[(j0+1)*20 + c4*2 + 1], KLu[(j0+1)*20 + c4*2 + 1]);
            k1[c4] = make_float4(xy.x, xy.y, zw.x, zw.y);
        }
        #pragma unroll 4
        for (int pi = pi0; pi < pi0 + 8; pi++) {
            const int r = ((pi >> 3) - phj + 7)*15 + ((pi & 7) - pwj + 7);
            float s0 = 0.f, s1 = 0.f;
            #pragma unroll
            for (int c4 = 0; c4 < 8; c4++) {
                uint2 e = *(const uint2*)(QEb + r*TS + c4*4);
                float2 e01 = upk(e.x), e23 = upk(e.y);
                s0 += k0[c4].x*e01.x + k0[c4].y*e01.y + k0[c4].z*e23.x + k0[c4].w*e23.y;
                s1 += k1[c4].x*e01.x + k1[c4].y*e01.y + k1[c4].z*e23.x + k1[c4].w*e23.y;
            }
            float2* d0 = (float2*)(sA + (2*pi)*AS + j0);
            float2* d1 = (float2*)(sA + (2*pi+1)*AS + j0);
            float2 t0 = *d0, t1 = *d1;
            t0.x += s0; t0.y += s1; *d0 = t0;
            t1.x += s0; t1.y += s1; *d1 = t1;
        }
    }
    __syncthreads();

    // ---- fused softmax + bf16 emit + pair-sum (in place), 8 rows per warp ----
    {
        const int w = wid, l = lane;
        for (int ii = 0; ii < 8; ii++) {
            const int i = w*8 + ii;
            float2 v01 = *(const float2*)(sA + i*AS + 2*l);
            float2 v23 = *(const float2*)(sA + i*AS + 64 + 2*l);
            float m = fmaxf(fmaxf(v01.x, v01.y), fmaxf(v23.x, v23.y));
            #pragma unroll
            for (int off = 16; off; off >>= 1) m = fmaxf(m, __shfl_xor_sync(~0u, m, off));
            float e0 = __expf(v01.x - m), e1 = __expf(v01.y - m);
            float e2 = __expf(v23.x - m), e3 = __expf(v23.y - m);
            float s = e0 + e1 + e2 + e3;
            #pragma unroll
            for (int off = 16; off; off >>= 1) s += __shfl_xor_sync(~0u, s, off);
            const float inv = 1.f / s;
            e0 *= inv; e1 *= inv; e2 *= inv; e3 *= inv;
            AHu[i*68 + l]      = pkhi(e0, e1);
            ALu[i*68 + l]      = pklo(e0, e1);
            AHu[i*68 + 32 + l] = pkhi(e2, e3);
            ALu[i*68 + 32 + l] = pklo(e2, e3);
            sA[i*AS + l]       = e0 + e1;
            sA[i*AS + 32 + l]  = e2 + e3;
        }
    }
    __syncthreads();

    // ---- scalar v_embed term (8 threads/pixel-pair, 4 channels each) -> sOE ----
    {
        const int p = tid >> 3, c0 = (tid & 7) << 2;
        const int phi = p >> 3, pwi = p & 7, i0 = 2*p;
        float4 a0 = {0,0,0,0}, a1 = {0,0,0,0};
        #pragma unroll 4
        for (int pj = 0; pj < 64; pj++) {
            const float s0 = sA[i0*AS + pj];
            const float s1 = sA[(i0+1)*AS + pj];
            const int r = (phi - (pj >> 3) + 7)*15 + (pwi - (pj & 7) + 7);
            uint2 ea = *(const uint2*)(VEb + r*TS + c0);
            float2 e0 = upk(ea.x), e1 = upk(ea.y);
            a0.x += s0*e0.x; a0.y += s0*e0.y; a0.z += s0*e1.x; a0.w += s0*e1.y;
            a1.x += s1*e0.x; a1.y += s1*e0.y; a1.z += s1*e1.x; a1.w += s1*e1.y;
        }
        *(float4*)(sOE + i0*ES + c0)     = a0;
        *(float4*)(sOE + (i0+1)*ES + c0) = a1;
    }
    __syncthreads();

    // ---- AV via mma.sync (16 warps: 16-row x 16-col tiles) + embed partial + store ----
    {
        const int rblk = (wid >> 1)*16, ntb = (wid & 1)*2;
        const int r = lane >> 2, cq = lane & 3;
        float d[2][4];
        #pragma unroll
        for (int nt = 0; nt < 2; nt++)
            #pragma unroll
            for (int e = 0; e < 4; e++) d[nt][e] = 0.f;
        #pragma unroll
        for (int kt = 0; kt < 8; kt++) {
            const int a0i = (rblk + r)*68 + kt*8 + cq;
            const int a1i = (rblk + r + 8)*68 + kt*8 + cq;
            uint32_t ah0 = AHu[a0i], ah1 = AHu[a1i], ah2 = AHu[a0i + 4], ah3 = AHu[a1i + 4];
            uint32_t al0 = ALu[a0i], al1 = ALu[a1i], al2 = ALu[a0i + 4], al3 = ALu[a1i + 4];
            #pragma unroll
            for (int ntl = 0; ntl < 2; ntl++) {
                const int bidx = ((ntb + ntl)*8 + r)*68 + kt*8 + cq;
                uint32_t bh0 = VTHu[bidx], bh1 = VTHu[bidx + 4];
                uint32_t bl0 = VTLu[bidx], bl1 = VTLu[bidx + 4];
                mma_bf16(d[ntl], ah0, ah1, ah2, ah3, bh0, bh1);
                mma_bf16(d[ntl], al0, al1, al2, al3, bh0, bh1);
                mma_bf16(d[ntl], ah0, ah1, ah2, ah3, bl0, bl1);
            }
        }
        #pragma unroll
        for (int half = 0; half < 2; half++) {
            const int i = rblk + r + half*8;
            const int p = i >> 1, n = i & 1;
            const int gy = (wi*8 + (p >> 3) + SHIFT) & 127;
            const int gx = (wj*8 + (p & 7) + SHIFT) & 127;
            float* o = out + (size_t)((((b*128 + gy)*128 + gx)*2 + n)*128) + h*32;
            #pragma unroll
            for (int ntl = 0; ntl < 2; ntl++) {
                const int j = (ntb + ntl)*8 + cq*2;
                float2 e = *(const float2*)(sOE + i*ES + j);
                float2 rv;
                rv.x = d[ntl][half*2 + 0] + e.x;
                rv.y = d[ntl][half*2 + 1] + e.y;
                *(float2*)(o + j) = rv;
            }
        }
    }
}

extern "C" void kernel_launch(void* const* d_in, const int* in_sizes, int n_in,
                              void* d_out, int out_size)
{
    const float* qkv  = (const float*)d_in[0];
    const float* mask = (const float*)d_in[1];
    const float* rpe  = (const float*)d_in[2];
    cudaFuncSetAttribute(swin_attn_kernel,
                         cudaFuncAttributeMaxDynamicSharedMemorySize, SMEM_BYTES);
    dim3 grid(1024, 4);
    swin_attn_kernel<<<grid, 512, SMEM_BYTES>>>(qkv, mask, rpe, (float*)d_out);
}